// round 3
// baseline (speedup 1.0000x reference)
#include <cuda_runtime.h>
#include <math.h>

#define NROWS 16384
#define CDIM  512
#define DDIM  2048

#define BM 128
#define BN 128
#define BK 8
#define TM 8
#define TN 8
#define NTHREADS 256

// Scratch (ping-pong c buffers + residual). Static device arrays: no allocation.
__device__ float g_cA[(size_t)NROWS * DDIM];
__device__ float g_cB[(size_t)NROWS * DDIM];
__device__ float g_r [(size_t)NROWS * CDIM];

__global__ void zero_losses_kernel(float* rl, float* cl) {
    *rl = 0.0f;
    *cl = 0.0f;
}

// ---------------------------------------------------------------------------
// Gradient step ("NT" GEMM): acc[n,d] = sum_c A[n,c] * W[d,c]   (K = CDIM)
// epilogue:  v = (c_in ? alpha*c_in + beta*cpre_in : 0) + 0.1*acc - 0.01
//            c_out = max(v, 0);  optional c_loss += 0.1 * sum(c_out)
// ---------------------------------------------------------------------------
__global__ __launch_bounds__(NTHREADS, 2)
void fista_step_kernel(const float* __restrict__ A,
                       const float* __restrict__ W,
                       const float* __restrict__ c_in,
                       const float* __restrict__ cpre_in,
                       float alpha, float beta,
                       float* __restrict__ c_out,
                       float* __restrict__ closs)
{
    __shared__ float As[2][BK][BM];
    __shared__ float Bs[2][BK][BN + 4];
    __shared__ float red[NTHREADS];

    const int K = CDIM;
    const int tid = threadIdx.x;
    const int tx = tid & 15;
    const int ty = tid >> 4;
    const int rowBase = blockIdx.y * BM;
    const int colBase = blockIdx.x * BN;

    const int lrow = tid >> 1;          // 0..127
    const int lcol = (tid & 1) * 4;     // 0 or 4

    const float* Aptr = A + (size_t)(rowBase + lrow) * K + lcol;
    const float* Bptr = W + (size_t)(colBase + lrow) * K + lcol;

    float4 aReg = *(const float4*)Aptr;
    float4 bReg = *(const float4*)Bptr;
    As[0][lcol + 0][lrow] = aReg.x;
    As[0][lcol + 1][lrow] = aReg.y;
    As[0][lcol + 2][lrow] = aReg.z;
    As[0][lcol + 3][lrow] = aReg.w;
    Bs[0][lcol + 0][lrow] = bReg.x;
    Bs[0][lcol + 1][lrow] = bReg.y;
    Bs[0][lcol + 2][lrow] = bReg.z;
    Bs[0][lcol + 3][lrow] = bReg.w;
    __syncthreads();

    float acc[TM][TN];
    #pragma unroll
    for (int i = 0; i < TM; i++)
        #pragma unroll
        for (int j = 0; j < TN; j++) acc[i][j] = 0.0f;

    const int ntiles = K / BK;
    for (int t = 0; t < ntiles; ++t) {
        const int cur = t & 1;
        if (t + 1 < ntiles) {
            aReg = *(const float4*)(Aptr + (t + 1) * BK);
            bReg = *(const float4*)(Bptr + (t + 1) * BK);
        }
        #pragma unroll
        for (int kk = 0; kk < BK; ++kk) {
            float4 a0 = *(const float4*)&As[cur][kk][ty * TM];
            float4 a1 = *(const float4*)&As[cur][kk][ty * TM + 4];
            float4 b0 = *(const float4*)&Bs[cur][kk][tx * TN];
            float4 b1 = *(const float4*)&Bs[cur][kk][tx * TN + 4];
            float a[TM] = {a0.x, a0.y, a0.z, a0.w, a1.x, a1.y, a1.z, a1.w};
            float b[TN] = {b0.x, b0.y, b0.z, b0.w, b1.x, b1.y, b1.z, b1.w};
            #pragma unroll
            for (int i = 0; i < TM; i++)
                #pragma unroll
                for (int j = 0; j < TN; j++)
                    acc[i][j] = fmaf(a[i], b[j], acc[i][j]);
        }
        if (t + 1 < ntiles) {
            const int nxt = cur ^ 1;
            As[nxt][lcol + 0][lrow] = aReg.x;
            As[nxt][lcol + 1][lrow] = aReg.y;
            As[nxt][lcol + 2][lrow] = aReg.z;
            As[nxt][lcol + 3][lrow] = aReg.w;
            Bs[nxt][lcol + 0][lrow] = bReg.x;
            Bs[nxt][lcol + 1][lrow] = bReg.y;
            Bs[nxt][lcol + 2][lrow] = bReg.z;
            Bs[nxt][lcol + 3][lrow] = bReg.w;
        }
        __syncthreads();
    }

    float lsum = 0.0f;
    #pragma unroll
    for (int i = 0; i < TM; ++i) {
        const size_t off = (size_t)(rowBase + ty * TM + i) * DDIM + colBase + tx * TN;
        float v[TN];
        #pragma unroll
        for (int j = 0; j < TN; ++j) v[j] = fmaf(0.1f, acc[i][j], -0.01f);
        if (c_in) {
            float4 c0 = *(const float4*)(c_in + off);
            float4 c1 = *(const float4*)(c_in + off + 4);
            float cv[TN] = {c0.x, c0.y, c0.z, c0.w, c1.x, c1.y, c1.z, c1.w};
            #pragma unroll
            for (int j = 0; j < TN; ++j) v[j] = fmaf(alpha, cv[j], v[j]);
            if (beta != 0.0f) {
                float4 p0 = *(const float4*)(cpre_in + off);
                float4 p1 = *(const float4*)(cpre_in + off + 4);
                float pv[TN] = {p0.x, p0.y, p0.z, p0.w, p1.x, p1.y, p1.z, p1.w};
                #pragma unroll
                for (int j = 0; j < TN; ++j) v[j] = fmaf(beta, pv[j], v[j]);
            }
        }
        #pragma unroll
        for (int j = 0; j < TN; ++j) {
            v[j] = fmaxf(v[j], 0.0f);
            lsum += v[j];
        }
        *(float4*)(c_out + off)     = make_float4(v[0], v[1], v[2], v[3]);
        *(float4*)(c_out + off + 4) = make_float4(v[4], v[5], v[6], v[7]);
    }

    if (closs) {
        red[tid] = lsum;
        __syncthreads();
        #pragma unroll
        for (int s = NTHREADS / 2; s > 0; s >>= 1) {
            if (tid < s) red[tid] += red[tid + s];
            __syncthreads();
        }
        if (tid == 0) atomicAdd(closs, 0.1f * red[0]);
    }
}

// ---------------------------------------------------------------------------
// Residual ("NN" GEMM): acc[n,c] = sum_d Cm[n,d] * W[d,c]   (K = DDIM)
// epilogue:  r = x - acc;  write r;  optional xp = acc;  optional r_loss += r^2
// ---------------------------------------------------------------------------
__global__ __launch_bounds__(NTHREADS, 2)
void residual_kernel(const float* __restrict__ Cm,
                     const float* __restrict__ W,
                     const float* __restrict__ X,
                     float* __restrict__ Rout,
                     float* __restrict__ XPout,
                     float* __restrict__ rloss)
{
    __shared__ float As[2][BK][BM];
    __shared__ float Bs[2][BK][BN + 4];
    __shared__ float red[NTHREADS];

    const int K = DDIM;
    const int tid = threadIdx.x;
    const int tx = tid & 15;
    const int ty = tid >> 4;
    const int rowBase = blockIdx.y * BM;
    const int colBase = blockIdx.x * BN;

    const int lrow = tid >> 1;          // A tile: 0..127
    const int lcol = (tid & 1) * 4;
    const int brow = tid >> 5;          // B tile: 0..7
    const int bcol = (tid & 31) * 4;    // 0..124

    const float* Aptr = Cm + (size_t)(rowBase + lrow) * K + lcol;
    const float* Bptr = W + (size_t)brow * CDIM + colBase + bcol;

    float4 aReg = *(const float4*)Aptr;
    float4 bReg = *(const float4*)Bptr;
    As[0][lcol + 0][lrow] = aReg.x;
    As[0][lcol + 1][lrow] = aReg.y;
    As[0][lcol + 2][lrow] = aReg.z;
    As[0][lcol + 3][lrow] = aReg.w;
    *(float4*)&Bs[0][brow][bcol] = bReg;
    __syncthreads();

    float acc[TM][TN];
    #pragma unroll
    for (int i = 0; i < TM; i++)
        #pragma unroll
        for (int j = 0; j < TN; j++) acc[i][j] = 0.0f;

    const int ntiles = K / BK;
    for (int t = 0; t < ntiles; ++t) {
        const int cur = t & 1;
        if (t + 1 < ntiles) {
            aReg = *(const float4*)(Aptr + (t + 1) * BK);
            bReg = *(const float4*)(Bptr + (size_t)(t + 1) * BK * CDIM);
        }
        #pragma unroll
        for (int kk = 0; kk < BK; ++kk) {
            float4 a0 = *(const float4*)&As[cur][kk][ty * TM];
            float4 a1 = *(const float4*)&As[cur][kk][ty * TM + 4];
            float4 b0 = *(const float4*)&Bs[cur][kk][tx * TN];
            float4 b1 = *(const float4*)&Bs[cur][kk][tx * TN + 4];
            float a[TM] = {a0.x, a0.y, a0.z, a0.w, a1.x, a1.y, a1.z, a1.w};
            float b[TN] = {b0.x, b0.y, b0.z, b0.w, b1.x, b1.y, b1.z, b1.w};
            #pragma unroll
            for (int i = 0; i < TM; i++)
                #pragma unroll
                for (int j = 0; j < TN; j++)
                    acc[i][j] = fmaf(a[i], b[j], acc[i][j]);
        }
        if (t + 1 < ntiles) {
            const int nxt = cur ^ 1;
            As[nxt][lcol + 0][lrow] = aReg.x;
            As[nxt][lcol + 1][lrow] = aReg.y;
            As[nxt][lcol + 2][lrow] = aReg.z;
            As[nxt][lcol + 3][lrow] = aReg.w;
            *(float4*)&Bs[nxt][brow][bcol] = bReg;
        }
        __syncthreads();
    }

    float lsum = 0.0f;
    #pragma unroll
    for (int i = 0; i < TM; ++i) {
        const size_t off = (size_t)(rowBase + ty * TM + i) * CDIM + colBase + tx * TN;
        float4 x0 = *(const float4*)(X + off);
        float4 x1 = *(const float4*)(X + off + 4);
        float xv[TN] = {x0.x, x0.y, x0.z, x0.w, x1.x, x1.y, x1.z, x1.w};
        float v[TN];
        #pragma unroll
        for (int j = 0; j < TN; ++j) {
            v[j] = xv[j] - acc[i][j];
            lsum = fmaf(v[j], v[j], lsum);
        }
        *(float4*)(Rout + off)     = make_float4(v[0], v[1], v[2], v[3]);
        *(float4*)(Rout + off + 4) = make_float4(v[4], v[5], v[6], v[7]);
        if (XPout) {
            *(float4*)(XPout + off)     = make_float4(acc[i][0], acc[i][1], acc[i][2], acc[i][3]);
            *(float4*)(XPout + off + 4) = make_float4(acc[i][4], acc[i][5], acc[i][6], acc[i][7]);
        }
    }

    if (rloss) {
        red[tid] = lsum;
        __syncthreads();
        #pragma unroll
        for (int s = NTHREADS / 2; s > 0; s >>= 1) {
            if (tid < s) red[tid] += red[tid + s];
            __syncthreads();
        }
        if (tid == 0) atomicAdd(rloss, red[0]);
    }
}

extern "C" void kernel_launch(void* const* d_in, const int* in_sizes, int n_in,
                              void* d_out, int out_size)
{
    (void)in_sizes; (void)n_in; (void)out_size;
    const float* x = (const float*)d_in[0];       // [8,2048,512] -> [16384,512]
    const float* W = (const float*)d_in[1];       // [2048,512]

    float* out      = (float*)d_out;
    float* out_c    = out;                                          // 16384*2048
    float* out_xp   = out_c  + (size_t)NROWS * DDIM;                // 16384*512
    float* out_r    = out_xp + (size_t)NROWS * CDIM;                // 16384*512
    float* out_rl   = out_r  + (size_t)NROWS * CDIM;                // 1
    float* out_cl   = out_rl + 1;                                   // 1

    float *cA, *cB, *rbuf;
    cudaGetSymbolAddress((void**)&cA, g_cA);
    cudaGetSymbolAddress((void**)&cB, g_cB);
    cudaGetSymbolAddress((void**)&rbuf, g_r);

    // FISTA momentum coefficients (double precision on host)
    float al[5] = {0, 0, 0, 0, 0}, be[5] = {0, 0, 0, 0, 0};
    {
        double tp = (sqrt(5.0) + 1.0) / 2.0;
        for (int i = 2; i < 5; i++) {
            double tn = (sqrt(1.0 + 4.0 * tp * tp) + 1.0) / 2.0;
            al[i] = (float)((tp + tn - 1.0) / tn);
            be[i] = (float)((1.0 - tp) / tn);
            tp = tn;
        }
    }

    dim3 blk(NTHREADS);
    dim3 grdStep(DDIM / BN, NROWS / BM);   // (16,128)
    dim3 grdRes (CDIM / BN, NROWS / BM);   // (4,128)

    zero_losses_kernel<<<1, 1>>>(out_rl, out_cl);

    // i = 0: c = max(0.1 * x@W^T - 0.01, 0)
    fista_step_kernel<<<grdStep, blk>>>(x, W, nullptr, nullptr, 0.f, 0.f, cA, nullptr);

    // i = 1: r = x - c@W;  c = max(c + 0.1 * r@W^T - 0.01, 0)
    residual_kernel<<<grdRes, blk>>>(cA, W, x, rbuf, nullptr, nullptr);
    fista_step_kernel<<<grdStep, blk>>>(rbuf, W, cA, cA, 1.f, 0.f, cB, nullptr);
    // state: c = cB, c_pre = cA

    // i = 2
    residual_kernel<<<grdRes, blk>>>(cB, W, x, rbuf, nullptr, nullptr);
    fista_step_kernel<<<grdStep, blk>>>(rbuf, W, cB, cA, al[2], be[2], cA, nullptr);
    // state: c = cA, c_pre = cB

    // i = 3
    residual_kernel<<<grdRes, blk>>>(cA, W, x, rbuf, nullptr, nullptr);
    fista_step_kernel<<<grdStep, blk>>>(rbuf, W, cA, cB, al[3], be[3], cB, nullptr);
    // state: c = cB, c_pre = cA

    // i = 4 (final step writes c straight into d_out + c_loss)
    residual_kernel<<<grdRes, blk>>>(cB, W, x, rbuf, nullptr, nullptr);
    fista_step_kernel<<<grdStep, blk>>>(rbuf, W, cB, cA, al[4], be[4], out_c, out_cl);

    // Final reconstruction: xp = c@W, r = x - xp, r_loss = sum(r^2)
    residual_kernel<<<grdRes, blk>>>(out_c, W, x, out_r, out_xp, out_rl);
}

// round 12
// speedup vs baseline: 1.8099x; 1.8099x over previous
#include <cuda_runtime.h>
#include <cuda_bf16.h>
#include <math.h>
#include <stdint.h>

#define NROWS 16384
#define CDIM  512
#define DDIM  2048

#define BM 128
#define BN 128
#define BK 32                    // k elements per pipeline stage
#define STAGES 4
#define ROW_BYTES 80             // 32 bf16 = 64B data + 16B pad (conflict-free)
#define TILE_BYTES (128 * ROW_BYTES)        // 10 KB per plane
#define STAGE_BYTES (4 * TILE_BYTES)        // Ah, Al, Bh, Bl = 40 KB
#define SMEM_BYTES (STAGES * STAGE_BYTES)   // 160 KB

// ---------------------------------------------------------------------------
// Static scratch (no allocation allowed). All activations stored as bf16
// hi/lo plane pairs; value = hi + lo reconstructs fp32 to ~2^-18.
// ---------------------------------------------------------------------------
__device__ __nv_bfloat16 g_xh [(size_t)NROWS * CDIM], g_xl [(size_t)NROWS * CDIM];
__device__ __nv_bfloat16 g_rh [(size_t)NROWS * CDIM], g_rl [(size_t)NROWS * CDIM];
__device__ __nv_bfloat16 g_cAh[(size_t)NROWS * DDIM], g_cAl[(size_t)NROWS * DDIM];
__device__ __nv_bfloat16 g_cBh[(size_t)NROWS * DDIM], g_cBl[(size_t)NROWS * DDIM];
__device__ __nv_bfloat16 g_Wh [(size_t)DDIM * CDIM],  g_Wl [(size_t)DDIM * CDIM];
__device__ __nv_bfloat16 g_Wth[(size_t)CDIM * DDIM],  g_Wtl[(size_t)CDIM * DDIM];

// ---------------------------------------------------------------------------
// PTX helpers (family-common sm_80+ only: cp.async, mma.sync — NO tcgen05)
// ---------------------------------------------------------------------------
__device__ __forceinline__ uint32_t smem_u32(const void* p) {
    return (uint32_t)__cvta_generic_to_shared(p);
}
__device__ __forceinline__ void cp16(uint32_t saddr, const void* gaddr) {
    asm volatile("cp.async.cg.shared.global [%0], [%1], 16;"
                 :: "r"(saddr), "l"(gaddr) : "memory");
}
__device__ __forceinline__ void cp_commit() {
    asm volatile("cp.async.commit_group;" ::: "memory");
}
#define CP_WAIT_GROUP(n) asm volatile("cp.async.wait_group %0;" :: "n"(n) : "memory")

__device__ __forceinline__ uint32_t lds_u32(uint32_t addr) {
    uint32_t v;
    asm("ld.shared.b32 %0, [%1];" : "=r"(v) : "r"(addr));
    return v;
}
__device__ __forceinline__ void mma_bf16(float* c, const uint32_t* a,
                                         uint32_t b0, uint32_t b1) {
    asm("mma.sync.aligned.m16n8k16.row.col.f32.bf16.bf16.f32 "
        "{%0,%1,%2,%3}, {%4,%5,%6,%7}, {%8,%9}, {%0,%1,%2,%3};"
        : "+f"(c[0]), "+f"(c[1]), "+f"(c[2]), "+f"(c[3])
        : "r"(a[0]), "r"(a[1]), "r"(a[2]), "r"(a[3]), "r"(b0), "r"(b1));
}
__device__ __forceinline__ void split_bf16(float v, __nv_bfloat16& h, __nv_bfloat16& l) {
    h = __float2bfloat16(v);
    l = __float2bfloat16(v - __bfloat162float(h));
}

// ---------------------------------------------------------------------------
// Small kernels
// ---------------------------------------------------------------------------
__global__ void zero_losses_kernel(float* rl, float* cl) { *rl = 0.0f; *cl = 0.0f; }

__global__ void prep_w_kernel(const float* __restrict__ W) {
    int i = blockIdx.x * blockDim.x + threadIdx.x;
    if (i < DDIM * CDIM) {
        __nv_bfloat16 h, l;
        split_bf16(W[i], h, l);
        g_Wh[i] = h; g_Wl[i] = l;
        int d = i / CDIM, c = i % CDIM;
        g_Wth[(size_t)c * DDIM + d] = h;
        g_Wtl[(size_t)c * DDIM + d] = l;
    }
}
__global__ void prep_x_kernel(const float* __restrict__ X) {
    int i = blockIdx.x * blockDim.x + threadIdx.x;
    if (i < NROWS * CDIM) {
        __nv_bfloat16 h, l;
        split_bf16(X[i], h, l);
        g_xh[i] = h; g_xl[i] = l;
    }
}

// ---------------------------------------------------------------------------
// Unified bf16-split GEMM (mma.sync m16n8k16, 3-product hi/lo) + fused FISTA
// epilogue.  D[128x128 tile] = (Ah+Al)[NROWS x K] @ (Bh+Bl)[Ntot x K]^T
//
// mode 0 (step):     v = relu(0.1*acc - 0.01 + alpha*cin + beta*cpre)
//                    write (outH,outL) split; optional fp32 outF; closs += 0.1*sum
// mode 1 (residual): r = x - acc
//                    optional (outH,outL)=split(r); out2=acc(xp); outF=r; rloss+=r^2
// ---------------------------------------------------------------------------
__global__ __launch_bounds__(256, 1)
void fista_mma_kernel(const __nv_bfloat16* __restrict__ Ah, const __nv_bfloat16* __restrict__ Al,
                      const __nv_bfloat16* __restrict__ Bh, const __nv_bfloat16* __restrict__ Bl,
                      int K, int nChunks, int Ntot, int mode,
                      const __nv_bfloat16* __restrict__ cInH, const __nv_bfloat16* __restrict__ cInL,
                      const __nv_bfloat16* __restrict__ cPreH, const __nv_bfloat16* __restrict__ cPreL,
                      float alpha, float beta,
                      __nv_bfloat16* __restrict__ outH, __nv_bfloat16* __restrict__ outL,
                      float* __restrict__ outF, float* __restrict__ out2,
                      const float* __restrict__ Xres, float* __restrict__ loss)
{
    extern __shared__ char dyn_smem[];
    __shared__ float s_red[256];

    const int tid = threadIdx.x;
    const int lane = tid & 31, wid = tid >> 5;
    const int g = lane >> 2, tig = lane & 3;
    const int warpM = wid & 1, warpN = wid >> 1;       // 2 x 4 warps, 64x32 each
    const int rowBase = blockIdx.y * BM;
    const int colBase = blockIdx.x * BN;
    const uint32_t sBase = smem_u32(dyn_smem);

    float acc[4][4][4];                                 // [mi][ni][frag]
    #pragma unroll
    for (int mi = 0; mi < 4; mi++)
        #pragma unroll
        for (int ni = 0; ni < 4; ni++)
            #pragma unroll
            for (int q = 0; q < 4; q++) acc[mi][ni][q] = 0.0f;

    // ---- stage loader: 4 planes x 128 rows x 64B, each thread 8 cp16 ----
    // Each cp16 moves 16 bytes = 8 bf16; segment c4 covers elements [c4*8, c4*8+8).
    auto load_stage = [&](int t) {
        const uint32_t stB = sBase + (t % STAGES) * STAGE_BYTES;
        const int k0 = t * BK;
        const __nv_bfloat16* gp[4] = {Ah, Al, Bh, Bl};
        const int rb[4] = {rowBase, rowBase, colBase, colBase};
        #pragma unroll
        for (int p = 0; p < 4; p++) {
            #pragma unroll
            for (int j = 0; j < 2; j++) {
                int idx = tid * 2 + j;                  // 0..511
                int row = idx >> 2, c4 = idx & 3;
                const __nv_bfloat16* src = gp[p] + (size_t)(rb[p] + row) * K + k0 + c4 * 8;
                cp16(stB + p * TILE_BYTES + row * ROW_BYTES + c4 * 16, src);
            }
        }
    };

    // ---- prologue ----
    for (int t = 0; t < STAGES - 1 && t < nChunks; t++) { load_stage(t); cp_commit(); }

    // ---- mainloop ----
    for (int t = 0; t < nChunks; t++) {
        CP_WAIT_GROUP(STAGES - 2);
        __syncthreads();
        const int pf = t + STAGES - 1;
        if (pf < nChunks) load_stage(pf);
        cp_commit();

        const uint32_t stB = sBase + (t % STAGES) * STAGE_BYTES;
        const uint32_t aH = stB, aL = stB + TILE_BYTES;
        const uint32_t bH = stB + 2 * TILE_BYTES, bL = stB + 3 * TILE_BYTES;

        #pragma unroll
        for (int ks = 0; ks < 2; ks++) {                // two k16 steps per BK=32
            const uint32_t koff = ks * 32 + tig * 4;
            uint32_t ah[4][4], al[4][4];
            #pragma unroll
            for (int mi = 0; mi < 4; mi++) {
                uint32_t ad = (uint32_t)(warpM * 64 + mi * 16 + g) * ROW_BYTES + koff;
                ah[mi][0] = lds_u32(aH + ad);       ah[mi][1] = lds_u32(aH + ad + 8 * ROW_BYTES);
                ah[mi][2] = lds_u32(aH + ad + 16);  ah[mi][3] = lds_u32(aH + ad + 8 * ROW_BYTES + 16);
                al[mi][0] = lds_u32(aL + ad);       al[mi][1] = lds_u32(aL + ad + 8 * ROW_BYTES);
                al[mi][2] = lds_u32(aL + ad + 16);  al[mi][3] = lds_u32(aL + ad + 8 * ROW_BYTES + 16);
            }
            #pragma unroll
            for (int ni = 0; ni < 4; ni++) {
                uint32_t bd = (uint32_t)(warpN * 32 + ni * 8 + g) * ROW_BYTES + koff;
                uint32_t bh0 = lds_u32(bH + bd), bh1 = lds_u32(bH + bd + 16);
                uint32_t bl0 = lds_u32(bL + bd), bl1 = lds_u32(bL + bd + 16);
                #pragma unroll
                for (int mi = 0; mi < 4; mi++) {
                    mma_bf16(acc[mi][ni], ah[mi], bh0, bh1);   // hi*hi
                    mma_bf16(acc[mi][ni], ah[mi], bl0, bl1);   // hi*lo
                    mma_bf16(acc[mi][ni], al[mi], bh0, bh1);   // lo*hi
                }
            }
        }
    }

    // ---- fused epilogue ----
    float lsum = 0.0f;
    #pragma unroll
    for (int mi = 0; mi < 4; mi++) {
        #pragma unroll
        for (int ni = 0; ni < 4; ni++) {
            const int col = colBase + warpN * 32 + ni * 8 + 2 * tig;
            #pragma unroll
            for (int half = 0; half < 2; half++) {
                const int row = rowBase + warpM * 64 + mi * 16 + g + half * 8;
                const float v0 = acc[mi][ni][half * 2 + 0];
                const float v1 = acc[mi][ni][half * 2 + 1];
                const size_t off = (size_t)row * Ntot + col;

                if (mode == 0) {
                    float w0 = fmaf(0.1f, v0, -0.01f);
                    float w1 = fmaf(0.1f, v1, -0.01f);
                    if (cInH) {
                        __nv_bfloat162 ch = *(const __nv_bfloat162*)(cInH + off);
                        __nv_bfloat162 cl = *(const __nv_bfloat162*)(cInL + off);
                        w0 = fmaf(alpha, __bfloat162float(ch.x) + __bfloat162float(cl.x), w0);
                        w1 = fmaf(alpha, __bfloat162float(ch.y) + __bfloat162float(cl.y), w1);
                        if (beta != 0.0f) {
                            __nv_bfloat162 ph = *(const __nv_bfloat162*)(cPreH + off);
                            __nv_bfloat162 pl = *(const __nv_bfloat162*)(cPreL + off);
                            w0 = fmaf(beta, __bfloat162float(ph.x) + __bfloat162float(pl.x), w0);
                            w1 = fmaf(beta, __bfloat162float(ph.y) + __bfloat162float(pl.y), w1);
                        }
                    }
                    w0 = fmaxf(w0, 0.0f);
                    w1 = fmaxf(w1, 0.0f);
                    lsum += w0 + w1;
                    __nv_bfloat16 h0, l0, h1, l1;
                    split_bf16(w0, h0, l0);
                    split_bf16(w1, h1, l1);
                    *(__nv_bfloat162*)(outH + off) = __nv_bfloat162(h0, h1);
                    *(__nv_bfloat162*)(outL + off) = __nv_bfloat162(l0, l1);
                    if (outF) *(float2*)(outF + off) = make_float2(w0, w1);
                } else {
                    float2 xv = *(const float2*)(Xres + off);
                    float r0 = xv.x - v0, r1 = xv.y - v1;
                    lsum = fmaf(r0, r0, fmaf(r1, r1, lsum));
                    if (outH) {
                        __nv_bfloat16 h0, l0, h1, l1;
                        split_bf16(r0, h0, l0);
                        split_bf16(r1, h1, l1);
                        *(__nv_bfloat162*)(outH + off) = __nv_bfloat162(h0, h1);
                        *(__nv_bfloat162*)(outL + off) = __nv_bfloat162(l0, l1);
                    }
                    if (out2) *(float2*)(out2 + off) = make_float2(v0, v1);
                    if (outF) *(float2*)(outF + off) = make_float2(r0, r1);
                }
            }
        }
    }

    if (loss) {
        s_red[tid] = lsum;
        __syncthreads();
        #pragma unroll
        for (int s = 128; s > 0; s >>= 1) {
            if (tid < s) s_red[tid] += s_red[tid + s];
            __syncthreads();
        }
        if (tid == 0) atomicAdd(loss, (mode == 0 ? 0.1f : 1.0f) * s_red[0]);
    }
}

// ---------------------------------------------------------------------------
extern "C" void kernel_launch(void* const* d_in, const int* in_sizes, int n_in,
                              void* d_out, int out_size)
{
    (void)in_sizes; (void)n_in; (void)out_size;
    const float* x = (const float*)d_in[0];       // [16384, 512]
    const float* W = (const float*)d_in[1];       // [2048, 512]

    float* out    = (float*)d_out;
    float* out_c  = out;
    float* out_xp = out_c  + (size_t)NROWS * DDIM;
    float* out_r  = out_xp + (size_t)NROWS * CDIM;
    float* out_rl = out_r  + (size_t)NROWS * CDIM;
    float* out_cl = out_rl + 1;

    __nv_bfloat16 *xh, *xl, *rh, *rl, *cAh, *cAl, *cBh, *cBl, *Wh, *Wl, *Wth, *Wtl;
    cudaGetSymbolAddress((void**)&xh,  g_xh);  cudaGetSymbolAddress((void**)&xl,  g_xl);
    cudaGetSymbolAddress((void**)&rh,  g_rh);  cudaGetSymbolAddress((void**)&rl,  g_rl);
    cudaGetSymbolAddress((void**)&cAh, g_cAh); cudaGetSymbolAddress((void**)&cAl, g_cAl);
    cudaGetSymbolAddress((void**)&cBh, g_cBh); cudaGetSymbolAddress((void**)&cBl, g_cBl);
    cudaGetSymbolAddress((void**)&Wh,  g_Wh);  cudaGetSymbolAddress((void**)&Wl,  g_Wl);
    cudaGetSymbolAddress((void**)&Wth, g_Wth); cudaGetSymbolAddress((void**)&Wtl, g_Wtl);

    cudaFuncSetAttribute(fista_mma_kernel,
                         cudaFuncAttributeMaxDynamicSharedMemorySize, SMEM_BYTES);

    // FISTA momentum coefficients
    float al_[5] = {0, 0, 0, 0, 0}, be_[5] = {0, 0, 0, 0, 0};
    {
        double tp = (sqrt(5.0) + 1.0) / 2.0;
        for (int i = 2; i < 5; i++) {
            double tn = (sqrt(1.0 + 4.0 * tp * tp) + 1.0) / 2.0;
            al_[i] = (float)((tp + tn - 1.0) / tn);
            be_[i] = (float)((1.0 - tp) / tn);
            tp = tn;
        }
    }

    const dim3 blk(256);
    const dim3 grdStep(DDIM / BN, NROWS / BM);   // (16, 128)
    const dim3 grdRes (CDIM / BN, NROWS / BM);   // (4, 128)
    const int NCC = CDIM / BK;                   // 16 chunks (K=512)
    const int NCD = DDIM / BK;                   // 64 chunks (K=2048)

    prep_w_kernel<<<(DDIM * CDIM + 255) / 256, 256>>>(W);
    prep_x_kernel<<<(NROWS * CDIM + 255) / 256, 256>>>(x);
    zero_losses_kernel<<<1, 1>>>(out_rl, out_cl);

    // i=0: c = relu(0.1 * x@W^T - 0.01) -> cA
    fista_mma_kernel<<<grdStep, blk, SMEM_BYTES>>>(
        xh, xl, Wh, Wl, CDIM, NCC, DDIM, 0,
        nullptr, nullptr, nullptr, nullptr, 0.f, 0.f,
        cAh, cAl, nullptr, nullptr, nullptr, nullptr);

    // i=1: r = x - cA@W ; c = relu(cA + 0.1*r@W^T - 0.01) -> cB
    fista_mma_kernel<<<grdRes, blk, SMEM_BYTES>>>(
        cAh, cAl, Wth, Wtl, DDIM, NCD, CDIM, 1,
        nullptr, nullptr, nullptr, nullptr, 0.f, 0.f,
        rh, rl, nullptr, nullptr, x, nullptr);
    fista_mma_kernel<<<grdStep, blk, SMEM_BYTES>>>(
        rh, rl, Wh, Wl, CDIM, NCC, DDIM, 0,
        cAh, cAl, cAh, cAl, 1.f, 0.f,
        cBh, cBl, nullptr, nullptr, nullptr, nullptr);
    // state: c = cB, c_pre = cA

    // i=2
    fista_mma_kernel<<<grdRes, blk, SMEM_BYTES>>>(
        cBh, cBl, Wth, Wtl, DDIM, NCD, CDIM, 1,
        nullptr, nullptr, nullptr, nullptr, 0.f, 0.f,
        rh, rl, nullptr, nullptr, x, nullptr);
    fista_mma_kernel<<<grdStep, blk, SMEM_BYTES>>>(
        rh, rl, Wh, Wl, CDIM, NCC, DDIM, 0,
        cBh, cBl, cAh, cAl, al_[2], be_[2],
        cAh, cAl, nullptr, nullptr, nullptr, nullptr);
    // state: c = cA, c_pre = cB

    // i=3
    fista_mma_kernel<<<grdRes, blk, SMEM_BYTES>>>(
        cAh, cAl, Wth, Wtl, DDIM, NCD, CDIM, 1,
        nullptr, nullptr, nullptr, nullptr, 0.f, 0.f,
        rh, rl, nullptr, nullptr, x, nullptr);
    fista_mma_kernel<<<grdStep, blk, SMEM_BYTES>>>(
        rh, rl, Wh, Wl, CDIM, NCC, DDIM, 0,
        cAh, cAl, cBh, cBl, al_[3], be_[3],
        cBh, cBl, nullptr, nullptr, nullptr, nullptr);
    // state: c = cB, c_pre = cA

    // i=4: final step; write c fp32 to out_c, split planes to cA, + c_loss
    fista_mma_kernel<<<grdRes, blk, SMEM_BYTES>>>(
        cBh, cBl, Wth, Wtl, DDIM, NCD, CDIM, 1,
        nullptr, nullptr, nullptr, nullptr, 0.f, 0.f,
        rh, rl, nullptr, nullptr, x, nullptr);
    fista_mma_kernel<<<grdStep, blk, SMEM_BYTES>>>(
        rh, rl, Wh, Wl, CDIM, NCC, DDIM, 0,
        cBh, cBl, cAh, cAl, al_[4], be_[4],
        cAh, cAl, out_c, nullptr, nullptr, out_cl);

    // final reconstruction: xp = c@W, r = x - xp, r_loss
    fista_mma_kernel<<<grdRes, blk, SMEM_BYTES>>>(
        cAh, cAl, Wth, Wtl, DDIM, NCD, CDIM, 1,
        nullptr, nullptr, nullptr, nullptr, 0.f, 0.f,
        nullptr, nullptr, out_r, out_xp, x, out_rl);
}

// round 13
// speedup vs baseline: 2.2667x; 1.2524x over previous
#include <cuda_runtime.h>
#include <cuda_bf16.h>
#include <math.h>
#include <stdint.h>

#define NROWS 16384
#define CDIM  512
#define DDIM  2048

#define BM 128
#define BN 128
#define BK 32                    // k elements per pipeline stage
#define STAGES 2
#define ROW_BYTES 80             // 32 bf16 = 64B data + 16B pad (conflict-free)
#define TILE_BYTES (128 * ROW_BYTES)        // 10 KB per plane
#define STAGE_BYTES (4 * TILE_BYTES)        // Ah, Al, Bh, Bl = 40 KB
#define SMEM_BYTES (STAGES * STAGE_BYTES)   // 80 KB -> 2 CTAs/SM

// ---------------------------------------------------------------------------
// Static scratch (no allocation allowed). All activations stored as bf16
// hi/lo plane pairs; value = hi + lo reconstructs fp32 to ~2^-18.
// ---------------------------------------------------------------------------
__device__ __nv_bfloat16 g_xh [(size_t)NROWS * CDIM], g_xl [(size_t)NROWS * CDIM];
__device__ __nv_bfloat16 g_rh [(size_t)NROWS * CDIM], g_rl [(size_t)NROWS * CDIM];
__device__ __nv_bfloat16 g_cAh[(size_t)NROWS * DDIM], g_cAl[(size_t)NROWS * DDIM];
__device__ __nv_bfloat16 g_cBh[(size_t)NROWS * DDIM], g_cBl[(size_t)NROWS * DDIM];
__device__ __nv_bfloat16 g_Wh [(size_t)DDIM * CDIM],  g_Wl [(size_t)DDIM * CDIM];
__device__ __nv_bfloat16 g_Wth[(size_t)CDIM * DDIM],  g_Wtl[(size_t)CDIM * DDIM];

// ---------------------------------------------------------------------------
// PTX helpers (family-common sm_80+: cp.async, mma.sync, ldmatrix)
// ---------------------------------------------------------------------------
__device__ __forceinline__ uint32_t smem_u32(const void* p) {
    return (uint32_t)__cvta_generic_to_shared(p);
}
__device__ __forceinline__ void cp16(uint32_t saddr, const void* gaddr) {
    asm volatile("cp.async.cg.shared.global [%0], [%1], 16;"
                 :: "r"(saddr), "l"(gaddr) : "memory");
}
__device__ __forceinline__ void cp_commit() {
    asm volatile("cp.async.commit_group;" ::: "memory");
}
#define CP_WAIT_GROUP(n) asm volatile("cp.async.wait_group %0;" :: "n"(n) : "memory")

__device__ __forceinline__ void ldsm_x4(uint32_t& r0, uint32_t& r1, uint32_t& r2,
                                        uint32_t& r3, uint32_t addr) {
    asm volatile("ldmatrix.sync.aligned.m8n8.x4.shared.b16 {%0,%1,%2,%3}, [%4];"
                 : "=r"(r0), "=r"(r1), "=r"(r2), "=r"(r3) : "r"(addr));
}
__device__ __forceinline__ void mma_bf16(float* c, const uint32_t* a,
                                         uint32_t b0, uint32_t b1) {
    asm("mma.sync.aligned.m16n8k16.row.col.f32.bf16.bf16.f32 "
        "{%0,%1,%2,%3}, {%4,%5,%6,%7}, {%8,%9}, {%0,%1,%2,%3};"
        : "+f"(c[0]), "+f"(c[1]), "+f"(c[2]), "+f"(c[3])
        : "r"(a[0]), "r"(a[1]), "r"(a[2]), "r"(a[3]), "r"(b0), "r"(b1));
}
__device__ __forceinline__ void split_bf16(float v, __nv_bfloat16& h, __nv_bfloat16& l) {
    h = __float2bfloat16(v);
    l = __float2bfloat16(v - __bfloat162float(h));
}

// ---------------------------------------------------------------------------
// Small kernels
// ---------------------------------------------------------------------------
__global__ void zero_losses_kernel(float* rl, float* cl) { *rl = 0.0f; *cl = 0.0f; }

__global__ void prep_w_kernel(const float* __restrict__ W) {
    int i = blockIdx.x * blockDim.x + threadIdx.x;
    if (i < DDIM * CDIM) {
        __nv_bfloat16 h, l;
        split_bf16(W[i], h, l);
        g_Wh[i] = h; g_Wl[i] = l;
        int d = i / CDIM, c = i % CDIM;
        g_Wth[(size_t)c * DDIM + d] = h;
        g_Wtl[(size_t)c * DDIM + d] = l;
    }
}
__global__ void prep_x_kernel(const float* __restrict__ X) {
    int i = blockIdx.x * blockDim.x + threadIdx.x;
    if (i < NROWS * CDIM) {
        __nv_bfloat16 h, l;
        split_bf16(X[i], h, l);
        g_xh[i] = h; g_xl[i] = l;
    }
}

// ---------------------------------------------------------------------------
// Unified bf16-split GEMM (mma.sync m16n8k16, 3-product hi/lo, ldmatrix) +
// fused FISTA epilogue.  D[128x128] = (Ah+Al)[NROWS x K] @ (Bh+Bl)[Ntot x K]^T
// ---------------------------------------------------------------------------
__global__ __launch_bounds__(256, 2)
void fista_mma_kernel(const __nv_bfloat16* __restrict__ Ah, const __nv_bfloat16* __restrict__ Al,
                      const __nv_bfloat16* __restrict__ Bh, const __nv_bfloat16* __restrict__ Bl,
                      int K, int nChunks, int Ntot, int mode,
                      const __nv_bfloat16* __restrict__ cInH, const __nv_bfloat16* __restrict__ cInL,
                      const __nv_bfloat16* __restrict__ cPreH, const __nv_bfloat16* __restrict__ cPreL,
                      float alpha, float beta,
                      __nv_bfloat16* __restrict__ outH, __nv_bfloat16* __restrict__ outL,
                      float* __restrict__ outF, float* __restrict__ out2,
                      const float* __restrict__ Xres, float* __restrict__ loss)
{
    extern __shared__ char dyn_smem[];
    __shared__ float s_red[256];

    const int tid = threadIdx.x;
    const int lane = tid & 31, wid = tid >> 5;
    const int g = lane >> 2, tig = lane & 3;
    const int warpM = wid & 1, warpN = wid >> 1;       // 2 x 4 warps, 64x32 each
    const int rowBase = blockIdx.y * BM;
    const int colBase = blockIdx.x * BN;
    const uint32_t sBase = smem_u32(dyn_smem);

    // Per-lane ldmatrix offsets (constant across tiles/chunks).
    // A tile (16x16): matrices ordered (r0-7,k0-7)(r8-15,k0-7)(r0-7,k8-15)(r8-15,k8-15)
    const uint32_t aLaneOff =
        (uint32_t)((lane & 7) + ((lane >> 3) & 1) * 8) * ROW_BYTES + ((lane >> 4) & 1) * 16;
    // B pair of n8 tiles: matrices (ni_lo,k0-7)(ni_lo,k8-15)(ni_hi,k0-7)(ni_hi,k8-15)
    const uint32_t bLaneOff =
        (uint32_t)((lane & 7) + ((lane >> 4) & 1) * 8) * ROW_BYTES + ((lane >> 3) & 1) * 16;

    float acc[4][4][4];                                 // [mi][ni][frag]
    #pragma unroll
    for (int mi = 0; mi < 4; mi++)
        #pragma unroll
        for (int ni = 0; ni < 4; ni++)
            #pragma unroll
            for (int q = 0; q < 4; q++) acc[mi][ni][q] = 0.0f;

    // ---- stage loader: 4 planes x 128 rows x 64B, each thread 8 cp16 ----
    auto load_stage = [&](int t) {
        const uint32_t stB = sBase + (t % STAGES) * STAGE_BYTES;
        const int k0 = t * BK;
        const __nv_bfloat16* gp[4] = {Ah, Al, Bh, Bl};
        const int rb[4] = {rowBase, rowBase, colBase, colBase};
        #pragma unroll
        for (int p = 0; p < 4; p++) {
            #pragma unroll
            for (int j = 0; j < 2; j++) {
                int idx = tid * 2 + j;                  // 0..511
                int row = idx >> 2, c4 = idx & 3;
                const __nv_bfloat16* src = gp[p] + (size_t)(rb[p] + row) * K + k0 + c4 * 8;
                cp16(stB + p * TILE_BYTES + row * ROW_BYTES + c4 * 16, src);
            }
        }
    };

    // ---- prologue: one stage in flight ----
    load_stage(0);
    cp_commit();

    // ---- mainloop ----
    for (int t = 0; t < nChunks; t++) {
        CP_WAIT_GROUP(0);                               // chunk t resident
        __syncthreads();
        const int pf = t + 1;
        if (pf < nChunks) load_stage(pf);               // overlaps compute of t
        cp_commit();

        const uint32_t stB = sBase + (t % STAGES) * STAGE_BYTES;
        const uint32_t aH = stB, aL = stB + TILE_BYTES;
        const uint32_t bH = stB + 2 * TILE_BYTES, bL = stB + 3 * TILE_BYTES;

        #pragma unroll
        for (int ks = 0; ks < 2; ks++) {                // two k16 steps per BK=32
            const uint32_t kOff = ks * 32;
            uint32_t ah[4][4], al[4][4];
            #pragma unroll
            for (int mi = 0; mi < 4; mi++) {
                const uint32_t tOff = (uint32_t)(warpM * 64 + mi * 16) * ROW_BYTES + kOff + aLaneOff;
                ldsm_x4(ah[mi][0], ah[mi][1], ah[mi][2], ah[mi][3], aH + tOff);
                ldsm_x4(al[mi][0], al[mi][1], al[mi][2], al[mi][3], aL + tOff);
            }
            #pragma unroll
            for (int np = 0; np < 2; np++) {            // ni pair {2np, 2np+1}
                const uint32_t bOff = (uint32_t)(warpN * 32 + np * 16) * ROW_BYTES + kOff + bLaneOff;
                uint32_t bh0, bh1, bh2, bh3, bl0, bl1, bl2, bl3;
                ldsm_x4(bh0, bh1, bh2, bh3, bH + bOff);
                ldsm_x4(bl0, bl1, bl2, bl3, bL + bOff);
                #pragma unroll
                for (int mi = 0; mi < 4; mi++) {
                    mma_bf16(acc[mi][2 * np],     ah[mi], bh0, bh1);   // hi*hi
                    mma_bf16(acc[mi][2 * np],     ah[mi], bl0, bl1);   // hi*lo
                    mma_bf16(acc[mi][2 * np],     al[mi], bh0, bh1);   // lo*hi
                    mma_bf16(acc[mi][2 * np + 1], ah[mi], bh2, bh3);
                    mma_bf16(acc[mi][2 * np + 1], ah[mi], bl2, bl3);
                    mma_bf16(acc[mi][2 * np + 1], al[mi], bh2, bh3);
                }
            }
        }
    }

    // ---- fused epilogue ----
    float lsum = 0.0f;
    #pragma unroll
    for (int mi = 0; mi < 4; mi++) {
        #pragma unroll
        for (int ni = 0; ni < 4; ni++) {
            const int col = colBase + warpN * 32 + ni * 8 + 2 * tig;
            #pragma unroll
            for (int half = 0; half < 2; half++) {
                const int row = rowBase + warpM * 64 + mi * 16 + g + half * 8;
                const float v0 = acc[mi][ni][half * 2 + 0];
                const float v1 = acc[mi][ni][half * 2 + 1];
                const size_t off = (size_t)row * Ntot + col;

                if (mode == 0) {
                    float w0 = fmaf(0.1f, v0, -0.01f);
                    float w1 = fmaf(0.1f, v1, -0.01f);
                    if (cInH) {
                        __nv_bfloat162 ch = *(const __nv_bfloat162*)(cInH + off);
                        __nv_bfloat162 cl = *(const __nv_bfloat162*)(cInL + off);
                        w0 = fmaf(alpha, __bfloat162float(ch.x) + __bfloat162float(cl.x), w0);
                        w1 = fmaf(alpha, __bfloat162float(ch.y) + __bfloat162float(cl.y), w1);
                        if (beta != 0.0f) {
                            __nv_bfloat162 ph = *(const __nv_bfloat162*)(cPreH + off);
                            __nv_bfloat162 pl = *(const __nv_bfloat162*)(cPreL + off);
                            w0 = fmaf(beta, __bfloat162float(ph.x) + __bfloat162float(pl.x), w0);
                            w1 = fmaf(beta, __bfloat162float(ph.y) + __bfloat162float(pl.y), w1);
                        }
                    }
                    w0 = fmaxf(w0, 0.0f);
                    w1 = fmaxf(w1, 0.0f);
                    lsum += w0 + w1;
                    __nv_bfloat16 h0, l0, h1, l1;
                    split_bf16(w0, h0, l0);
                    split_bf16(w1, h1, l1);
                    *(__nv_bfloat162*)(outH + off) = __nv_bfloat162(h0, h1);
                    *(__nv_bfloat162*)(outL + off) = __nv_bfloat162(l0, l1);
                    if (outF) *(float2*)(outF + off) = make_float2(w0, w1);
                } else {
                    float2 xv = *(const float2*)(Xres + off);
                    float r0 = xv.x - v0, r1 = xv.y - v1;
                    lsum = fmaf(r0, r0, fmaf(r1, r1, lsum));
                    if (outH) {
                        __nv_bfloat16 h0, l0, h1, l1;
                        split_bf16(r0, h0, l0);
                        split_bf16(r1, h1, l1);
                        *(__nv_bfloat162*)(outH + off) = __nv_bfloat162(h0, h1);
                        *(__nv_bfloat162*)(outL + off) = __nv_bfloat162(l0, l1);
                    }
                    if (out2) *(float2*)(out2 + off) = make_float2(v0, v1);
                    if (outF) *(float2*)(outF + off) = make_float2(r0, r1);
                }
            }
        }
    }

    if (loss) {
        s_red[tid] = lsum;
        __syncthreads();
        #pragma unroll
        for (int s = 128; s > 0; s >>= 1) {
            if (tid < s) s_red[tid] += s_red[tid + s];
            __syncthreads();
        }
        if (tid == 0) atomicAdd(loss, (mode == 0 ? 0.1f : 1.0f) * s_red[0]);
    }
}

// ---------------------------------------------------------------------------
extern "C" void kernel_launch(void* const* d_in, const int* in_sizes, int n_in,
                              void* d_out, int out_size)
{
    (void)in_sizes; (void)n_in; (void)out_size;
    const float* x = (const float*)d_in[0];       // [16384, 512]
    const float* W = (const float*)d_in[1];       // [2048, 512]

    float* out    = (float*)d_out;
    float* out_c  = out;
    float* out_xp = out_c  + (size_t)NROWS * DDIM;
    float* out_r  = out_xp + (size_t)NROWS * CDIM;
    float* out_rl = out_r  + (size_t)NROWS * CDIM;
    float* out_cl = out_rl + 1;

    __nv_bfloat16 *xh, *xl, *rh, *rl, *cAh, *cAl, *cBh, *cBl, *Wh, *Wl, *Wth, *Wtl;
    cudaGetSymbolAddress((void**)&xh,  g_xh);  cudaGetSymbolAddress((void**)&xl,  g_xl);
    cudaGetSymbolAddress((void**)&rh,  g_rh);  cudaGetSymbolAddress((void**)&rl,  g_rl);
    cudaGetSymbolAddress((void**)&cAh, g_cAh); cudaGetSymbolAddress((void**)&cAl, g_cAl);
    cudaGetSymbolAddress((void**)&cBh, g_cBh); cudaGetSymbolAddress((void**)&cBl, g_cBl);
    cudaGetSymbolAddress((void**)&Wh,  g_Wh);  cudaGetSymbolAddress((void**)&Wl,  g_Wl);
    cudaGetSymbolAddress((void**)&Wth, g_Wth); cudaGetSymbolAddress((void**)&Wtl, g_Wtl);

    cudaFuncSetAttribute(fista_mma_kernel,
                         cudaFuncAttributeMaxDynamicSharedMemorySize, SMEM_BYTES);

    // FISTA momentum coefficients
    float al_[5] = {0, 0, 0, 0, 0}, be_[5] = {0, 0, 0, 0, 0};
    {
        double tp = (sqrt(5.0) + 1.0) / 2.0;
        for (int i = 2; i < 5; i++) {
            double tn = (sqrt(1.0 + 4.0 * tp * tp) + 1.0) / 2.0;
            al_[i] = (float)((tp + tn - 1.0) / tn);
            be_[i] = (float)((1.0 - tp) / tn);
            tp = tn;
        }
    }

    const dim3 blk(256);
    const dim3 grdStep(DDIM / BN, NROWS / BM);   // (16, 128)
    const dim3 grdRes (CDIM / BN, NROWS / BM);   // (4, 128)
    const int NCC = CDIM / BK;                   // 16 chunks (K=512)
    const int NCD = DDIM / BK;                   // 64 chunks (K=2048)

    prep_w_kernel<<<(DDIM * CDIM + 255) / 256, 256>>>(W);
    prep_x_kernel<<<(NROWS * CDIM + 255) / 256, 256>>>(x);
    zero_losses_kernel<<<1, 1>>>(out_rl, out_cl);

    // i=0: c = relu(0.1 * x@W^T - 0.01) -> cA
    fista_mma_kernel<<<grdStep, blk, SMEM_BYTES>>>(
        xh, xl, Wh, Wl, CDIM, NCC, DDIM, 0,
        nullptr, nullptr, nullptr, nullptr, 0.f, 0.f,
        cAh, cAl, nullptr, nullptr, nullptr, nullptr);

    // i=1: r = x - cA@W ; c = relu(cA + 0.1*r@W^T - 0.01) -> cB
    fista_mma_kernel<<<grdRes, blk, SMEM_BYTES>>>(
        cAh, cAl, Wth, Wtl, DDIM, NCD, CDIM, 1,
        nullptr, nullptr, nullptr, nullptr, 0.f, 0.f,
        rh, rl, nullptr, nullptr, x, nullptr);
    fista_mma_kernel<<<grdStep, blk, SMEM_BYTES>>>(
        rh, rl, Wh, Wl, CDIM, NCC, DDIM, 0,
        cAh, cAl, cAh, cAl, 1.f, 0.f,
        cBh, cBl, nullptr, nullptr, nullptr, nullptr);
    // state: c = cB, c_pre = cA

    // i=2
    fista_mma_kernel<<<grdRes, blk, SMEM_BYTES>>>(
        cBh, cBl, Wth, Wtl, DDIM, NCD, CDIM, 1,
        nullptr, nullptr, nullptr, nullptr, 0.f, 0.f,
        rh, rl, nullptr, nullptr, x, nullptr);
    fista_mma_kernel<<<grdStep, blk, SMEM_BYTES>>>(
        rh, rl, Wh, Wl, CDIM, NCC, DDIM, 0,
        cBh, cBl, cAh, cAl, al_[2], be_[2],
        cAh, cAl, nullptr, nullptr, nullptr, nullptr);
    // state: c = cA, c_pre = cB

    // i=3
    fista_mma_kernel<<<grdRes, blk, SMEM_BYTES>>>(
        cAh, cAl, Wth, Wtl, DDIM, NCD, CDIM, 1,
        nullptr, nullptr, nullptr, nullptr, 0.f, 0.f,
        rh, rl, nullptr, nullptr, x, nullptr);
    fista_mma_kernel<<<grdStep, blk, SMEM_BYTES>>>(
        rh, rl, Wh, Wl, CDIM, NCC, DDIM, 0,
        cAh, cAl, cBh, cBl, al_[3], be_[3],
        cBh, cBl, nullptr, nullptr, nullptr, nullptr);
    // state: c = cB, c_pre = cA

    // i=4: final step; write c fp32 to out_c, split planes to cA, + c_loss
    fista_mma_kernel<<<grdRes, blk, SMEM_BYTES>>>(
        cBh, cBl, Wth, Wtl, DDIM, NCD, CDIM, 1,
        nullptr, nullptr, nullptr, nullptr, 0.f, 0.f,
        rh, rl, nullptr, nullptr, x, nullptr);
    fista_mma_kernel<<<grdStep, blk, SMEM_BYTES>>>(
        rh, rl, Wh, Wl, CDIM, NCC, DDIM, 0,
        cBh, cBl, cAh, cAl, al_[4], be_[4],
        cAh, cAl, out_c, nullptr, nullptr, out_cl);

    // final reconstruction: xp = c@W, r = x - xp, r_loss
    fista_mma_kernel<<<grdRes, blk, SMEM_BYTES>>>(
        cAh, cAl, Wth, Wtl, DDIM, NCD, CDIM, 1,
        nullptr, nullptr, nullptr, nullptr, 0.f, 0.f,
        nullptr, nullptr, out_r, out_xp, x, out_rl);
}

// round 14
// speedup vs baseline: 2.4311x; 1.0725x over previous
#include <cuda_runtime.h>
#include <cuda_bf16.h>
#include <math.h>
#include <stdint.h>

#define NROWS 16384
#define CDIM  512
#define DDIM  2048

#define BM 128
#define BN 128
#define BK 32                    // k elements per pipeline stage
#define STAGES 3
#define TILE_BYTES (128 * 64)               // 8 KB per plane (swizzled, no pad)
#define STAGE_BYTES (4 * TILE_BYTES)        // Ah, Al, Bh, Bl = 32 KB
#define SMEM_BYTES (STAGES * STAGE_BYTES)   // 96 KB -> 2 CTAs/SM

// Swizzled smem layout: two logical 64B rows per 128B physical row.
// phys(row, seg) = (row>>1)*128 + ((((row&1)<<2)|seg) ^ ((row>>1)&7))*16
// Conflict-free for both cp.async 16B writes and ldmatrix m8n8 reads.
__device__ __forceinline__ uint32_t swz(int row, int seg) {
    return (uint32_t)((row >> 1) * 128 +
                      (((((row & 1) << 2) | seg) ^ ((row >> 1) & 7)) << 4));
}

// ---------------------------------------------------------------------------
// Static scratch (no allocation allowed). Activations stored as bf16 hi/lo
// plane pairs; value = hi + lo reconstructs fp32 to ~2^-18.
// ---------------------------------------------------------------------------
__device__ __nv_bfloat16 g_xh [(size_t)NROWS * CDIM], g_xl [(size_t)NROWS * CDIM];
__device__ __nv_bfloat16 g_rh [(size_t)NROWS * CDIM], g_rl [(size_t)NROWS * CDIM];
__device__ __nv_bfloat16 g_cAh[(size_t)NROWS * DDIM], g_cAl[(size_t)NROWS * DDIM];
__device__ __nv_bfloat16 g_cBh[(size_t)NROWS * DDIM], g_cBl[(size_t)NROWS * DDIM];
__device__ __nv_bfloat16 g_Wh [(size_t)DDIM * CDIM],  g_Wl [(size_t)DDIM * CDIM];
__device__ __nv_bfloat16 g_Wth[(size_t)CDIM * DDIM],  g_Wtl[(size_t)CDIM * DDIM];

// ---------------------------------------------------------------------------
// PTX helpers (family-common sm_80+: cp.async, mma.sync, ldmatrix)
// ---------------------------------------------------------------------------
__device__ __forceinline__ uint32_t smem_u32(const void* p) {
    return (uint32_t)__cvta_generic_to_shared(p);
}
__device__ __forceinline__ void cp16(uint32_t saddr, const void* gaddr) {
    asm volatile("cp.async.cg.shared.global [%0], [%1], 16;"
                 :: "r"(saddr), "l"(gaddr) : "memory");
}
__device__ __forceinline__ void cp_commit() {
    asm volatile("cp.async.commit_group;" ::: "memory");
}
#define CP_WAIT_GROUP(n) asm volatile("cp.async.wait_group %0;" :: "n"(n) : "memory")

__device__ __forceinline__ void ldsm_x4(uint32_t& r0, uint32_t& r1, uint32_t& r2,
                                        uint32_t& r3, uint32_t addr) {
    asm volatile("ldmatrix.sync.aligned.m8n8.x4.shared.b16 {%0,%1,%2,%3}, [%4];"
                 : "=r"(r0), "=r"(r1), "=r"(r2), "=r"(r3) : "r"(addr));
}
__device__ __forceinline__ void mma_bf16(float* c, const uint32_t* a,
                                         uint32_t b0, uint32_t b1) {
    asm("mma.sync.aligned.m16n8k16.row.col.f32.bf16.bf16.f32 "
        "{%0,%1,%2,%3}, {%4,%5,%6,%7}, {%8,%9}, {%0,%1,%2,%3};"
        : "+f"(c[0]), "+f"(c[1]), "+f"(c[2]), "+f"(c[3])
        : "r"(a[0]), "r"(a[1]), "r"(a[2]), "r"(a[3]), "r"(b0), "r"(b1));
}
__device__ __forceinline__ void split_bf16(float v, __nv_bfloat16& h, __nv_bfloat16& l) {
    h = __float2bfloat16(v);
    l = __float2bfloat16(v - __bfloat162float(h));
}

// ---------------------------------------------------------------------------
// Small kernels
// ---------------------------------------------------------------------------
__global__ void zero_losses_kernel(float* rl, float* cl) { *rl = 0.0f; *cl = 0.0f; }

__global__ void prep_w_kernel(const float* __restrict__ W) {
    int i = blockIdx.x * blockDim.x + threadIdx.x;
    if (i < DDIM * CDIM) {
        __nv_bfloat16 h, l;
        split_bf16(W[i], h, l);
        g_Wh[i] = h; g_Wl[i] = l;
        int d = i / CDIM, c = i % CDIM;
        g_Wth[(size_t)c * DDIM + d] = h;
        g_Wtl[(size_t)c * DDIM + d] = l;
    }
}
__global__ void prep_x_kernel(const float* __restrict__ X) {
    int i = blockIdx.x * blockDim.x + threadIdx.x;
    if (i < NROWS * CDIM) {
        __nv_bfloat16 h, l;
        split_bf16(X[i], h, l);
        g_xh[i] = h; g_xl[i] = l;
    }
}

// ---------------------------------------------------------------------------
// Unified bf16-split GEMM (mma.sync m16n8k16, 3-product hi/lo, ldmatrix,
// swizzled smem, 3-stage cp.async pipeline) + fused FISTA epilogue.
// D[128x128] = (Ah+Al)[NROWS x K] @ (Bh+Bl)[Ntot x K]^T
// ---------------------------------------------------------------------------
__global__ __launch_bounds__(256, 2)
void fista_mma_kernel(const __nv_bfloat16* __restrict__ Ah, const __nv_bfloat16* __restrict__ Al,
                      const __nv_bfloat16* __restrict__ Bh, const __nv_bfloat16* __restrict__ Bl,
                      int K, int nChunks, int Ntot, int mode,
                      const __nv_bfloat16* __restrict__ cInH, const __nv_bfloat16* __restrict__ cInL,
                      const __nv_bfloat16* __restrict__ cPreH, const __nv_bfloat16* __restrict__ cPreL,
                      float alpha, float beta,
                      __nv_bfloat16* __restrict__ outH, __nv_bfloat16* __restrict__ outL,
                      float* __restrict__ outF, float* __restrict__ out2,
                      const float* __restrict__ Xres, float* __restrict__ loss)
{
    extern __shared__ char dyn_smem[];
    __shared__ float s_red[256];

    const int tid = threadIdx.x;
    const int lane = tid & 31, wid = tid >> 5;
    const int g = lane >> 4 ? 0 : 0;  // placeholder to keep naming clear below
    (void)g;
    const int gq = lane >> 2, tig = lane & 3;
    const int warpM = wid & 1, warpN = wid >> 1;       // 2 x 4 warps, 64x32 each
    const int rowBase = blockIdx.y * BM;
    const int colBase = blockIdx.x * BN;
    const uint32_t sBase = smem_u32(dyn_smem);

    // Per-lane ldmatrix swizzled offsets (constant across mi/np; XOR term is
    // invariant because tiles step by 16 rows = 8 physical rows).
    // A: matrices (r0-7,k0-7)(r8-15,k0-7)(r0-7,k8-15)(r8-15,k8-15)
    const int aRow = warpM * 64 + (lane & 7) + ((lane >> 3) & 1) * 8;
    const int aSegSel = (lane >> 4) & 1;
    const uint32_t aOff0 = swz(aRow, 0 + aSegSel);      // ks=0: segs {0,1}
    const uint32_t aOff1 = swz(aRow, 2 + aSegSel);      // ks=1: segs {2,3}
    // B: matrices (ni_lo,k0-7)(ni_lo,k8-15)(ni_hi,k0-7)(ni_hi,k8-15)
    const int bRow = warpN * 32 + (lane & 7) + ((lane >> 4) & 1) * 8;
    const int bSegSel = (lane >> 3) & 1;
    const uint32_t bOff0 = swz(bRow, 0 + bSegSel);
    const uint32_t bOff1 = swz(bRow, 2 + bSegSel);

    // Loader per-thread constants: each thread writes 2 consecutive 16B segs
    // of one row (row = tid>>1, segs {(2*tid)&3, ((2*tid)&3)+1}).
    const int ldRow = tid >> 1;
    const int ldSeg = (tid & 1) * 2;
    const uint32_t ldDst0 = swz(ldRow, ldSeg);
    const uint32_t ldDst1 = swz(ldRow, ldSeg + 1);
    const int ldKoff = ldSeg * 8;                       // element offset in k

    float acc[4][4][4];                                 // [mi][ni][frag]
    #pragma unroll
    for (int mi = 0; mi < 4; mi++)
        #pragma unroll
        for (int ni = 0; ni < 4; ni++)
            #pragma unroll
            for (int q = 0; q < 4; q++) acc[mi][ni][q] = 0.0f;

    // ---- stage loader: 4 planes x 128 rows x 64B ----
    auto load_stage = [&](int t) {
        const uint32_t stB = sBase + (t % STAGES) * STAGE_BYTES;
        const int k0 = t * BK + ldKoff;
        const __nv_bfloat16* gp[4] = {Ah, Al, Bh, Bl};
        const int rb[4] = {rowBase, rowBase, colBase, colBase};
        #pragma unroll
        for (int p = 0; p < 4; p++) {
            const __nv_bfloat16* src = gp[p] + (size_t)(rb[p] + ldRow) * K + k0;
            cp16(stB + p * TILE_BYTES + ldDst0, src);
            cp16(stB + p * TILE_BYTES + ldDst1, src + 8);
        }
    };

    // ---- prologue: two stages in flight ----
    load_stage(0); cp_commit();
    load_stage(1); cp_commit();

    // ---- mainloop ----
    for (int t = 0; t < nChunks; t++) {
        CP_WAIT_GROUP(1);                               // chunk t resident; t+1 may fly
        __syncthreads();
        const int pf = t + 2;
        if (pf < nChunks) load_stage(pf);
        cp_commit();

        const uint32_t stB = sBase + (t % STAGES) * STAGE_BYTES;
        const uint32_t aH = stB, aL = stB + TILE_BYTES;
        const uint32_t bH = stB + 2 * TILE_BYTES, bL = stB + 3 * TILE_BYTES;

        #pragma unroll
        for (int ks = 0; ks < 2; ks++) {                // two k16 steps per BK=32
            const uint32_t aOff = ks ? aOff1 : aOff0;
            const uint32_t bOff = ks ? bOff1 : bOff0;
            uint32_t ah[4][4], al[4][4];
            #pragma unroll
            for (int mi = 0; mi < 4; mi++) {
                ldsm_x4(ah[mi][0], ah[mi][1], ah[mi][2], ah[mi][3], aH + aOff + mi * 1024);
                ldsm_x4(al[mi][0], al[mi][1], al[mi][2], al[mi][3], aL + aOff + mi * 1024);
            }
            #pragma unroll
            for (int np = 0; np < 2; np++) {            // ni pair {2np, 2np+1}
                uint32_t bh0, bh1, bh2, bh3, bl0, bl1, bl2, bl3;
                ldsm_x4(bh0, bh1, bh2, bh3, bH + bOff + np * 1024);
                ldsm_x4(bl0, bl1, bl2, bl3, bL + bOff + np * 1024);
                #pragma unroll
                for (int mi = 0; mi < 4; mi++) {
                    mma_bf16(acc[mi][2 * np],     ah[mi], bh0, bh1);   // hi*hi
                    mma_bf16(acc[mi][2 * np],     ah[mi], bl0, bl1);   // hi*lo
                    mma_bf16(acc[mi][2 * np],     al[mi], bh0, bh1);   // lo*hi
                    mma_bf16(acc[mi][2 * np + 1], ah[mi], bh2, bh3);
                    mma_bf16(acc[mi][2 * np + 1], ah[mi], bl2, bl3);
                    mma_bf16(acc[mi][2 * np + 1], al[mi], bh2, bh3);
                }
            }
        }
    }

    // ---- fused epilogue ----
    float lsum = 0.0f;
    #pragma unroll
    for (int mi = 0; mi < 4; mi++) {
        #pragma unroll
        for (int ni = 0; ni < 4; ni++) {
            const int col = colBase + warpN * 32 + ni * 8 + 2 * tig;
            #pragma unroll
            for (int half = 0; half < 2; half++) {
                const int row = rowBase + warpM * 64 + mi * 16 + gq + half * 8;
                const float v0 = acc[mi][ni][half * 2 + 0];
                const float v1 = acc[mi][ni][half * 2 + 1];
                const size_t off = (size_t)row * Ntot + col;

                if (mode == 0) {
                    float w0 = fmaf(0.1f, v0, -0.01f);
                    float w1 = fmaf(0.1f, v1, -0.01f);
                    if (cInH) {
                        __nv_bfloat162 ch = *(const __nv_bfloat162*)(cInH + off);
                        __nv_bfloat162 cl = *(const __nv_bfloat162*)(cInL + off);
                        w0 = fmaf(alpha, __bfloat162float(ch.x) + __bfloat162float(cl.x), w0);
                        w1 = fmaf(alpha, __bfloat162float(ch.y) + __bfloat162float(cl.y), w1);
                        if (beta != 0.0f) {
                            __nv_bfloat162 ph = *(const __nv_bfloat162*)(cPreH + off);
                            __nv_bfloat162 pl = *(const __nv_bfloat162*)(cPreL + off);
                            w0 = fmaf(beta, __bfloat162float(ph.x) + __bfloat162float(pl.x), w0);
                            w1 = fmaf(beta, __bfloat162float(ph.y) + __bfloat162float(pl.y), w1);
                        }
                    }
                    w0 = fmaxf(w0, 0.0f);
                    w1 = fmaxf(w1, 0.0f);
                    lsum += w0 + w1;
                    __nv_bfloat16 h0, l0, h1, l1;
                    split_bf16(w0, h0, l0);
                    split_bf16(w1, h1, l1);
                    *(__nv_bfloat162*)(outH + off) = __nv_bfloat162(h0, h1);
                    *(__nv_bfloat162*)(outL + off) = __nv_bfloat162(l0, l1);
                    if (outF) *(float2*)(outF + off) = make_float2(w0, w1);
                } else {
                    float2 xv = *(const float2*)(Xres + off);
                    float r0 = xv.x - v0, r1 = xv.y - v1;
                    lsum = fmaf(r0, r0, fmaf(r1, r1, lsum));
                    if (outH) {
                        __nv_bfloat16 h0, l0, h1, l1;
                        split_bf16(r0, h0, l0);
                        split_bf16(r1, h1, l1);
                        *(__nv_bfloat162*)(outH + off) = __nv_bfloat162(h0, h1);
                        *(__nv_bfloat162*)(outL + off) = __nv_bfloat162(l0, l1);
                    }
                    if (out2) *(float2*)(out2 + off) = make_float2(v0, v1);
                    if (outF) *(float2*)(outF + off) = make_float2(r0, r1);
                }
            }
        }
    }

    if (loss) {
        s_red[tid] = lsum;
        __syncthreads();
        #pragma unroll
        for (int s = 128; s > 0; s >>= 1) {
            if (tid < s) s_red[tid] += s_red[tid + s];
            __syncthreads();
        }
        if (tid == 0) atomicAdd(loss, (mode == 0 ? 0.1f : 1.0f) * s_red[0]);
    }
}

// ---------------------------------------------------------------------------
extern "C" void kernel_launch(void* const* d_in, const int* in_sizes, int n_in,
                              void* d_out, int out_size)
{
    (void)in_sizes; (void)n_in; (void)out_size;
    const float* x = (const float*)d_in[0];       // [16384, 512]
    const float* W = (const float*)d_in[1];       // [2048, 512]

    float* out    = (float*)d_out;
    float* out_c  = out;
    float* out_xp = out_c  + (size_t)NROWS * DDIM;
    float* out_r  = out_xp + (size_t)NROWS * CDIM;
    float* out_rl = out_r  + (size_t)NROWS * CDIM;
    float* out_cl = out_rl + 1;

    __nv_bfloat16 *xh, *xl, *rh, *rl, *cAh, *cAl, *cBh, *cBl, *Wh, *Wl, *Wth, *Wtl;
    cudaGetSymbolAddress((void**)&xh,  g_xh);  cudaGetSymbolAddress((void**)&xl,  g_xl);
    cudaGetSymbolAddress((void**)&rh,  g_rh);  cudaGetSymbolAddress((void**)&rl,  g_rl);
    cudaGetSymbolAddress((void**)&cAh, g_cAh); cudaGetSymbolAddress((void**)&cAl, g_cAl);
    cudaGetSymbolAddress((void**)&cBh, g_cBh); cudaGetSymbolAddress((void**)&cBl, g_cBl);
    cudaGetSymbolAddress((void**)&Wh,  g_Wh);  cudaGetSymbolAddress((void**)&Wl,  g_Wl);
    cudaGetSymbolAddress((void**)&Wth, g_Wth); cudaGetSymbolAddress((void**)&Wtl, g_Wtl);

    cudaFuncSetAttribute(fista_mma_kernel,
                         cudaFuncAttributeMaxDynamicSharedMemorySize, SMEM_BYTES);

    // FISTA momentum coefficients
    float al_[5] = {0, 0, 0, 0, 0}, be_[5] = {0, 0, 0, 0, 0};
    {
        double tp = (sqrt(5.0) + 1.0) / 2.0;
        for (int i = 2; i < 5; i++) {
            double tn = (sqrt(1.0 + 4.0 * tp * tp) + 1.0) / 2.0;
            al_[i] = (float)((tp + tn - 1.0) / tn);
            be_[i] = (float)((1.0 - tp) / tn);
            tp = tn;
        }
    }

    const dim3 blk(256);
    const dim3 grdStep(DDIM / BN, NROWS / BM);   // (16, 128)
    const dim3 grdRes (CDIM / BN, NROWS / BM);   // (4, 128)
    const int NCC = CDIM / BK;                   // 16 chunks (K=512)
    const int NCD = DDIM / BK;                   // 64 chunks (K=2048)

    prep_w_kernel<<<(DDIM * CDIM + 255) / 256, 256>>>(W);
    prep_x_kernel<<<(NROWS * CDIM + 255) / 256, 256>>>(x);
    zero_losses_kernel<<<1, 1>>>(out_rl, out_cl);

    // i=0: c = relu(0.1 * x@W^T - 0.01) -> cA
    fista_mma_kernel<<<grdStep, blk, SMEM_BYTES>>>(
        xh, xl, Wh, Wl, CDIM, NCC, DDIM, 0,
        nullptr, nullptr, nullptr, nullptr, 0.f, 0.f,
        cAh, cAl, nullptr, nullptr, nullptr, nullptr);

    // i=1: r = x - cA@W ; c = relu(cA + 0.1*r@W^T - 0.01) -> cB
    fista_mma_kernel<<<grdRes, blk, SMEM_BYTES>>>(
        cAh, cAl, Wth, Wtl, DDIM, NCD, CDIM, 1,
        nullptr, nullptr, nullptr, nullptr, 0.f, 0.f,
        rh, rl, nullptr, nullptr, x, nullptr);
    fista_mma_kernel<<<grdStep, blk, SMEM_BYTES>>>(
        rh, rl, Wh, Wl, CDIM, NCC, DDIM, 0,
        cAh, cAl, cAh, cAl, 1.f, 0.f,
        cBh, cBl, nullptr, nullptr, nullptr, nullptr);
    // state: c = cB, c_pre = cA

    // i=2
    fista_mma_kernel<<<grdRes, blk, SMEM_BYTES>>>(
        cBh, cBl, Wth, Wtl, DDIM, NCD, CDIM, 1,
        nullptr, nullptr, nullptr, nullptr, 0.f, 0.f,
        rh, rl, nullptr, nullptr, x, nullptr);
    fista_mma_kernel<<<grdStep, blk, SMEM_BYTES>>>(
        rh, rl, Wh, Wl, CDIM, NCC, DDIM, 0,
        cBh, cBl, cAh, cAl, al_[2], be_[2],
        cAh, cAl, nullptr, nullptr, nullptr, nullptr);
    // state: c = cA, c_pre = cB

    // i=3
    fista_mma_kernel<<<grdRes, blk, SMEM_BYTES>>>(
        cAh, cAl, Wth, Wtl, DDIM, NCD, CDIM, 1,
        nullptr, nullptr, nullptr, nullptr, 0.f, 0.f,
        rh, rl, nullptr, nullptr, x, nullptr);
    fista_mma_kernel<<<grdStep, blk, SMEM_BYTES>>>(
        rh, rl, Wh, Wl, CDIM, NCC, DDIM, 0,
        cAh, cAl, cBh, cBl, al_[3], be_[3],
        cBh, cBl, nullptr, nullptr, nullptr, nullptr);
    // state: c = cB, c_pre = cA

    // i=4: final step; write c fp32 to out_c, split planes to cA, + c_loss
    fista_mma_kernel<<<grdRes, blk, SMEM_BYTES>>>(
        cBh, cBl, Wth, Wtl, DDIM, NCD, CDIM, 1,
        nullptr, nullptr, nullptr, nullptr, 0.f, 0.f,
        rh, rl, nullptr, nullptr, x, nullptr);
    fista_mma_kernel<<<grdStep, blk, SMEM_BYTES>>>(
        rh, rl, Wh, Wl, CDIM, NCC, DDIM, 0,
        cBh, cBl, cAh, cAl, al_[4], be_[4],
        cAh, cAl, out_c, nullptr, nullptr, out_cl);

    // final reconstruction: xp = c@W, r = x - xp, r_loss
    fista_mma_kernel<<<grdRes, blk, SMEM_BYTES>>>(
        cAh, cAl, Wth, Wtl, DDIM, NCD, CDIM, 1,
        nullptr, nullptr, nullptr, nullptr, 0.f, 0.f,
        nullptr, nullptr, out_r, out_xp, x, out_rl);
}

// round 15
// speedup vs baseline: 2.7388x; 1.1266x over previous
#include <cuda_runtime.h>
#include <cuda_bf16.h>
#include <math.h>
#include <stdint.h>

#define NROWS 16384
#define CDIM  512
#define DDIM  2048

#define BM 128
#define BN 64
#define BK 32                    // k elements per pipeline stage
#define STAGES 3
#define A_TILE (128 * 64)                   // 8 KB per A plane (swizzled 64B rows)
#define B_TILE (64 * 64)                    // 4 KB per B plane
#define STAGE_BYTES (2 * A_TILE + 2 * B_TILE)   // 24 KB
#define SMEM_BYTES (STAGES * STAGE_BYTES)       // 72 KB -> 3 CTAs/SM

// Swizzled smem layout: two logical 64B rows per 128B physical row.
// phys(row, seg) = (row>>1)*128 + ((((row&1)<<2)|seg) ^ ((row>>1)&7))*16
// Conflict-free for cp.async 16B writes and ldmatrix m8n8 reads.
__device__ __forceinline__ uint32_t swz(int row, int seg) {
    return (uint32_t)((row >> 1) * 128 +
                      (((((row & 1) << 2) | seg) ^ ((row >> 1) & 7)) << 4));
}

// ---------------------------------------------------------------------------
// Static scratch (no allocation allowed). Activations stored as bf16 hi/lo
// plane pairs; value = hi + lo reconstructs fp32 to ~2^-18.
// ---------------------------------------------------------------------------
__device__ __nv_bfloat16 g_xh [(size_t)NROWS * CDIM], g_xl [(size_t)NROWS * CDIM];
__device__ __nv_bfloat16 g_rh [(size_t)NROWS * CDIM], g_rl [(size_t)NROWS * CDIM];
__device__ __nv_bfloat16 g_cAh[(size_t)NROWS * DDIM], g_cAl[(size_t)NROWS * DDIM];
__device__ __nv_bfloat16 g_cBh[(size_t)NROWS * DDIM], g_cBl[(size_t)NROWS * DDIM];
__device__ __nv_bfloat16 g_Wh [(size_t)DDIM * CDIM],  g_Wl [(size_t)DDIM * CDIM];
__device__ __nv_bfloat16 g_Wth[(size_t)CDIM * DDIM],  g_Wtl[(size_t)CDIM * DDIM];

// ---------------------------------------------------------------------------
// PTX helpers (family-common sm_80+: cp.async, mma.sync, ldmatrix)
// ---------------------------------------------------------------------------
__device__ __forceinline__ uint32_t smem_u32(const void* p) {
    return (uint32_t)__cvta_generic_to_shared(p);
}
__device__ __forceinline__ void cp16(uint32_t saddr, const void* gaddr) {
    asm volatile("cp.async.cg.shared.global [%0], [%1], 16;"
                 :: "r"(saddr), "l"(gaddr) : "memory");
}
__device__ __forceinline__ void cp_commit() {
    asm volatile("cp.async.commit_group;" ::: "memory");
}
#define CP_WAIT_GROUP(n) asm volatile("cp.async.wait_group %0;" :: "n"(n) : "memory")

__device__ __forceinline__ void ldsm_x4(uint32_t& r0, uint32_t& r1, uint32_t& r2,
                                        uint32_t& r3, uint32_t addr) {
    asm volatile("ldmatrix.sync.aligned.m8n8.x4.shared.b16 {%0,%1,%2,%3}, [%4];"
                 : "=r"(r0), "=r"(r1), "=r"(r2), "=r"(r3) : "r"(addr));
}
__device__ __forceinline__ void mma_bf16(float* c, const uint32_t* a,
                                         uint32_t b0, uint32_t b1) {
    asm("mma.sync.aligned.m16n8k16.row.col.f32.bf16.bf16.f32 "
        "{%0,%1,%2,%3}, {%4,%5,%6,%7}, {%8,%9}, {%0,%1,%2,%3};"
        : "+f"(c[0]), "+f"(c[1]), "+f"(c[2]), "+f"(c[3])
        : "r"(a[0]), "r"(a[1]), "r"(a[2]), "r"(a[3]), "r"(b0), "r"(b1));
}
__device__ __forceinline__ void split_bf16(float v, __nv_bfloat16& h, __nv_bfloat16& l) {
    h = __float2bfloat16(v);
    l = __float2bfloat16(v - __bfloat162float(h));
}

// ---------------------------------------------------------------------------
// Small kernels
// ---------------------------------------------------------------------------
__global__ void zero_losses_kernel(float* rl, float* cl) { *rl = 0.0f; *cl = 0.0f; }

__global__ void prep_w_kernel(const float* __restrict__ W) {
    int i = blockIdx.x * blockDim.x + threadIdx.x;
    if (i < DDIM * CDIM) {
        __nv_bfloat16 h, l;
        split_bf16(W[i], h, l);
        g_Wh[i] = h; g_Wl[i] = l;
        int d = i / CDIM, c = i % CDIM;
        g_Wth[(size_t)c * DDIM + d] = h;
        g_Wtl[(size_t)c * DDIM + d] = l;
    }
}
__global__ void prep_x_kernel(const float* __restrict__ X) {
    int i = blockIdx.x * blockDim.x + threadIdx.x;
    if (i < NROWS * CDIM) {
        __nv_bfloat16 h, l;
        split_bf16(X[i], h, l);
        g_xh[i] = h; g_xl[i] = l;
    }
}

// ---------------------------------------------------------------------------
// Unified bf16-split GEMM (mma.sync m16n8k16, 3-product hi/lo, ldmatrix,
// swizzled smem, 3-stage cp.async pipeline, 128x64 tile, 3 CTAs/SM) +
// fused FISTA epilogue.  D = (Ah+Al)[NROWS x K] @ (Bh+Bl)[Ntot x K]^T
// ---------------------------------------------------------------------------
__global__ __launch_bounds__(256, 3)
void fista_mma_kernel(const __nv_bfloat16* __restrict__ Ah, const __nv_bfloat16* __restrict__ Al,
                      const __nv_bfloat16* __restrict__ Bh, const __nv_bfloat16* __restrict__ Bl,
                      int K, int nChunks, int Ntot, int mode,
                      const __nv_bfloat16* __restrict__ cInH, const __nv_bfloat16* __restrict__ cInL,
                      const __nv_bfloat16* __restrict__ cPreH, const __nv_bfloat16* __restrict__ cPreL,
                      float alpha, float beta,
                      __nv_bfloat16* __restrict__ outH, __nv_bfloat16* __restrict__ outL,
                      float* __restrict__ outF, float* __restrict__ out2,
                      const float* __restrict__ Xres, float* __restrict__ loss)
{
    extern __shared__ char dyn_smem[];
    __shared__ float s_red[256];

    const int tid = threadIdx.x;
    const int lane = tid & 31, wid = tid >> 5;
    const int gq = lane >> 2, tig = lane & 3;
    const int warpM = wid & 3, warpN = wid >> 2;       // 4 x 2 warps, 32x32 each
    const int rowBase = blockIdx.y * BM;
    const int colBase = blockIdx.x * BN;
    const uint32_t sBase = smem_u32(dyn_smem);

    // Per-lane ldmatrix swizzled offsets (XOR term invariant under +16-row steps).
    // A: matrices (r0-7,k0-7)(r8-15,k0-7)(r0-7,k8-15)(r8-15,k8-15)
    const int aRowL = (lane & 7) + ((lane >> 3) & 1) * 8;
    const int aSegSel = (lane >> 4) & 1;
    const uint32_t aOff0 = swz(aRowL, 0 + aSegSel);     // ks=0: segs {0,1}
    const uint32_t aOff1 = swz(aRowL, 2 + aSegSel);     // ks=1: segs {2,3}
    // B: matrices (n0-7,k0-7)(n0-7,k8-15)(n8-15,k0-7)(n8-15,k8-15)
    const int bRowL = (lane & 7) + ((lane >> 4) & 1) * 8;
    const int bSegSel = (lane >> 3) & 1;
    const uint32_t bOff0 = swz(bRowL, 0 + bSegSel);
    const uint32_t bOff1 = swz(bRowL, 2 + bSegSel);

    float acc[2][4][4];                                 // [mi][ni(n8)][frag]
    #pragma unroll
    for (int mi = 0; mi < 2; mi++)
        #pragma unroll
        for (int ni = 0; ni < 4; ni++)
            #pragma unroll
            for (int q = 0; q < 4; q++) acc[mi][ni][q] = 0.0f;

    // ---- stage loader: A 2x(128 rows), B 2x(64 rows), 64B/row, 6 cp16/thread ----
    auto load_stage = [&](int t) {
        const uint32_t stB = sBase + (t % STAGES) * STAGE_BYTES;
        const int k0 = t * BK;
        #pragma unroll
        for (int p = 0; p < 2; p++) {                   // A planes
            const __nv_bfloat16* base = p ? Al : Ah;
            #pragma unroll
            for (int i = 0; i < 2; i++) {
                int slot = tid + i * 256;               // 0..511
                int row = slot >> 2, seg = slot & 3;
                cp16(stB + p * A_TILE + swz(row, seg),
                     base + (size_t)(rowBase + row) * K + k0 + seg * 8);
            }
        }
        #pragma unroll
        for (int p = 0; p < 2; p++) {                   // B planes
            const __nv_bfloat16* base = p ? Bl : Bh;
            int row = tid >> 2, seg = tid & 3;          // 64 rows x 4 segs = 256
            cp16(stB + 2 * A_TILE + p * B_TILE + swz(row, seg),
                 base + (size_t)(colBase + row) * K + k0 + seg * 8);
        }
    };

    // ---- prologue: two stages in flight ----
    load_stage(0); cp_commit();
    load_stage(1); cp_commit();

    // ---- mainloop ----
    for (int t = 0; t < nChunks; t++) {
        CP_WAIT_GROUP(1);                               // chunk t resident; t+1 may fly
        __syncthreads();
        const int pf = t + 2;
        if (pf < nChunks) load_stage(pf);
        cp_commit();

        const uint32_t stB = sBase + (t % STAGES) * STAGE_BYTES;
        const uint32_t aH = stB + (uint32_t)warpM * 2048;            // 32 rows = 2048B
        const uint32_t aL = aH + A_TILE;
        const uint32_t bH = stB + 2 * A_TILE + (uint32_t)warpN * 2048;
        const uint32_t bL = bH + B_TILE;

        #pragma unroll
        for (int ks = 0; ks < 2; ks++) {                // two k16 steps per BK=32
            const uint32_t aOff = ks ? aOff1 : aOff0;
            const uint32_t bOff = ks ? bOff1 : bOff0;
            uint32_t ah[2][4], al[2][4];
            #pragma unroll
            for (int mi = 0; mi < 2; mi++) {
                ldsm_x4(ah[mi][0], ah[mi][1], ah[mi][2], ah[mi][3], aH + aOff + mi * 1024);
                ldsm_x4(al[mi][0], al[mi][1], al[mi][2], al[mi][3], aL + aOff + mi * 1024);
            }
            #pragma unroll
            for (int np = 0; np < 2; np++) {            // n8 pair {2np, 2np+1}
                uint32_t bh0, bh1, bh2, bh3, bl0, bl1, bl2, bl3;
                ldsm_x4(bh0, bh1, bh2, bh3, bH + bOff + np * 1024);
                ldsm_x4(bl0, bl1, bl2, bl3, bL + bOff + np * 1024);
                #pragma unroll
                for (int mi = 0; mi < 2; mi++) {
                    mma_bf16(acc[mi][2 * np],     ah[mi], bh0, bh1);   // hi*hi
                    mma_bf16(acc[mi][2 * np],     ah[mi], bl0, bl1);   // hi*lo
                    mma_bf16(acc[mi][2 * np],     al[mi], bh0, bh1);   // lo*hi
                    mma_bf16(acc[mi][2 * np + 1], ah[mi], bh2, bh3);
                    mma_bf16(acc[mi][2 * np + 1], ah[mi], bl2, bl3);
                    mma_bf16(acc[mi][2 * np + 1], al[mi], bh2, bh3);
                }
            }
        }
    }

    // ---- fused epilogue ----
    float lsum = 0.0f;
    #pragma unroll
    for (int mi = 0; mi < 2; mi++) {
        #pragma unroll
        for (int ni = 0; ni < 4; ni++) {
            const int col = colBase + warpN * 32 + ni * 8 + 2 * tig;
            #pragma unroll
            for (int half = 0; half < 2; half++) {
                const int row = rowBase + warpM * 32 + mi * 16 + gq + half * 8;
                const float v0 = acc[mi][ni][half * 2 + 0];
                const float v1 = acc[mi][ni][half * 2 + 1];
                const size_t off = (size_t)row * Ntot + col;

                if (mode == 0) {
                    float w0 = fmaf(0.1f, v0, -0.01f);
                    float w1 = fmaf(0.1f, v1, -0.01f);
                    if (cInH) {
                        __nv_bfloat162 ch = *(const __nv_bfloat162*)(cInH + off);
                        __nv_bfloat162 cl = *(const __nv_bfloat162*)(cInL + off);
                        w0 = fmaf(alpha, __bfloat162float(ch.x) + __bfloat162float(cl.x), w0);
                        w1 = fmaf(alpha, __bfloat162float(ch.y) + __bfloat162float(cl.y), w1);
                        if (beta != 0.0f) {
                            __nv_bfloat162 ph = *(const __nv_bfloat162*)(cPreH + off);
                            __nv_bfloat162 pl = *(const __nv_bfloat162*)(cPreL + off);
                            w0 = fmaf(beta, __bfloat162float(ph.x) + __bfloat162float(pl.x), w0);
                            w1 = fmaf(beta, __bfloat162float(ph.y) + __bfloat162float(pl.y), w1);
                        }
                    }
                    w0 = fmaxf(w0, 0.0f);
                    w1 = fmaxf(w1, 0.0f);
                    lsum += w0 + w1;
                    __nv_bfloat16 h0, l0, h1, l1;
                    split_bf16(w0, h0, l0);
                    split_bf16(w1, h1, l1);
                    *(__nv_bfloat162*)(outH + off) = __nv_bfloat162(h0, h1);
                    *(__nv_bfloat162*)(outL + off) = __nv_bfloat162(l0, l1);
                    if (outF) *(float2*)(outF + off) = make_float2(w0, w1);
                } else {
                    float2 xv = *(const float2*)(Xres + off);
                    float r0 = xv.x - v0, r1 = xv.y - v1;
                    lsum = fmaf(r0, r0, fmaf(r1, r1, lsum));
                    if (outH) {
                        __nv_bfloat16 h0, l0, h1, l1;
                        split_bf16(r0, h0, l0);
                        split_bf16(r1, h1, l1);
                        *(__nv_bfloat162*)(outH + off) = __nv_bfloat162(h0, h1);
                        *(__nv_bfloat162*)(outL + off) = __nv_bfloat162(l0, l1);
                    }
                    if (out2) *(float2*)(out2 + off) = make_float2(v0, v1);
                    if (outF) *(float2*)(outF + off) = make_float2(r0, r1);
                }
            }
        }
    }

    if (loss) {
        s_red[tid] = lsum;
        __syncthreads();
        #pragma unroll
        for (int s = 128; s > 0; s >>= 1) {
            if (tid < s) s_red[tid] += s_red[tid + s];
            __syncthreads();
        }
        if (tid == 0) atomicAdd(loss, (mode == 0 ? 0.1f : 1.0f) * s_red[0]);
    }
}

// ---------------------------------------------------------------------------
extern "C" void kernel_launch(void* const* d_in, const int* in_sizes, int n_in,
                              void* d_out, int out_size)
{
    (void)in_sizes; (void)n_in; (void)out_size;
    const float* x = (const float*)d_in[0];       // [16384, 512]
    const float* W = (const float*)d_in[1];       // [2048, 512]

    float* out    = (float*)d_out;
    float* out_c  = out;
    float* out_xp = out_c  + (size_t)NROWS * DDIM;
    float* out_r  = out_xp + (size_t)NROWS * CDIM;
    float* out_rl = out_r  + (size_t)NROWS * CDIM;
    float* out_cl = out_rl + 1;

    __nv_bfloat16 *xh, *xl, *rh, *rl, *cAh, *cAl, *cBh, *cBl, *Wh, *Wl, *Wth, *Wtl;
    cudaGetSymbolAddress((void**)&xh,  g_xh);  cudaGetSymbolAddress((void**)&xl,  g_xl);
    cudaGetSymbolAddress((void**)&rh,  g_rh);  cudaGetSymbolAddress((void**)&rl,  g_rl);
    cudaGetSymbolAddress((void**)&cAh, g_cAh); cudaGetSymbolAddress((void**)&cAl, g_cAl);
    cudaGetSymbolAddress((void**)&cBh, g_cBh); cudaGetSymbolAddress((void**)&cBl, g_cBl);
    cudaGetSymbolAddress((void**)&Wh,  g_Wh);  cudaGetSymbolAddress((void**)&Wl,  g_Wl);
    cudaGetSymbolAddress((void**)&Wth, g_Wth); cudaGetSymbolAddress((void**)&Wtl, g_Wtl);

    cudaFuncSetAttribute(fista_mma_kernel,
                         cudaFuncAttributeMaxDynamicSharedMemorySize, SMEM_BYTES);

    // FISTA momentum coefficients
    float al_[5] = {0, 0, 0, 0, 0}, be_[5] = {0, 0, 0, 0, 0};
    {
        double tp = (sqrt(5.0) + 1.0) / 2.0;
        for (int i = 2; i < 5; i++) {
            double tn = (sqrt(1.0 + 4.0 * tp * tp) + 1.0) / 2.0;
            al_[i] = (float)((tp + tn - 1.0) / tn);
            be_[i] = (float)((1.0 - tp) / tn);
            tp = tn;
        }
    }

    const dim3 blk(256);
    const dim3 grdStep(DDIM / BN, NROWS / BM);   // (32, 128)
    const dim3 grdRes (CDIM / BN, NROWS / BM);   // (8, 128)
    const int NCC = CDIM / BK;                   // 16 chunks (K=512)
    const int NCD = DDIM / BK;                   // 64 chunks (K=2048)

    prep_w_kernel<<<(DDIM * CDIM + 255) / 256, 256>>>(W);
    prep_x_kernel<<<(NROWS * CDIM + 255) / 256, 256>>>(x);
    zero_losses_kernel<<<1, 1>>>(out_rl, out_cl);

    // i=0: c = relu(0.1 * x@W^T - 0.01) -> cA
    fista_mma_kernel<<<grdStep, blk, SMEM_BYTES>>>(
        xh, xl, Wh, Wl, CDIM, NCC, DDIM, 0,
        nullptr, nullptr, nullptr, nullptr, 0.f, 0.f,
        cAh, cAl, nullptr, nullptr, nullptr, nullptr);

    // i=1: r = x - cA@W ; c = relu(cA + 0.1*r@W^T - 0.01) -> cB
    fista_mma_kernel<<<grdRes, blk, SMEM_BYTES>>>(
        cAh, cAl, Wth, Wtl, DDIM, NCD, CDIM, 1,
        nullptr, nullptr, nullptr, nullptr, 0.f, 0.f,
        rh, rl, nullptr, nullptr, x, nullptr);
    fista_mma_kernel<<<grdStep, blk, SMEM_BYTES>>>(
        rh, rl, Wh, Wl, CDIM, NCC, DDIM, 0,
        cAh, cAl, cAh, cAl, 1.f, 0.f,
        cBh, cBl, nullptr, nullptr, nullptr, nullptr);
    // state: c = cB, c_pre = cA

    // i=2
    fista_mma_kernel<<<grdRes, blk, SMEM_BYTES>>>(
        cBh, cBl, Wth, Wtl, DDIM, NCD, CDIM, 1,
        nullptr, nullptr, nullptr, nullptr, 0.f, 0.f,
        rh, rl, nullptr, nullptr, x, nullptr);
    fista_mma_kernel<<<grdStep, blk, SMEM_BYTES>>>(
        rh, rl, Wh, Wl, CDIM, NCC, DDIM, 0,
        cBh, cBl, cAh, cAl, al_[2], be_[2],
        cAh, cAl, nullptr, nullptr, nullptr, nullptr);
    // state: c = cA, c_pre = cB

    // i=3
    fista_mma_kernel<<<grdRes, blk, SMEM_BYTES>>>(
        cAh, cAl, Wth, Wtl, DDIM, NCD, CDIM, 1,
        nullptr, nullptr, nullptr, nullptr, 0.f, 0.f,
        rh, rl, nullptr, nullptr, x, nullptr);
    fista_mma_kernel<<<grdStep, blk, SMEM_BYTES>>>(
        rh, rl, Wh, Wl, CDIM, NCC, DDIM, 0,
        cAh, cAl, cBh, cBl, al_[3], be_[3],
        cBh, cBl, nullptr, nullptr, nullptr, nullptr);
    // state: c = cB, c_pre = cA

    // i=4: final step; write c fp32 to out_c, split planes to cA, + c_loss
    fista_mma_kernel<<<grdRes, blk, SMEM_BYTES>>>(
        cBh, cBl, Wth, Wtl, DDIM, NCD, CDIM, 1,
        nullptr, nullptr, nullptr, nullptr, 0.f, 0.f,
        rh, rl, nullptr, nullptr, x, nullptr);
    fista_mma_kernel<<<grdStep, blk, SMEM_BYTES>>>(
        rh, rl, Wh, Wl, CDIM, NCC, DDIM, 0,
        cBh, cBl, cAh, cAl, al_[4], be_[4],
        cAh, cAl, out_c, nullptr, nullptr, out_cl);

    // final reconstruction: xp = c@W, r = x - xp, r_loss
    fista_mma_kernel<<<grdRes, blk, SMEM_BYTES>>>(
        cAh, cAl, Wth, Wtl, DDIM, NCD, CDIM, 1,
        nullptr, nullptr, nullptr, nullptr, 0.f, 0.f,
        nullptr, nullptr, out_r, out_xp, x, out_rl);
}